// round 11
// baseline (speedup 1.0000x reference)
#include <cuda_runtime.h>
#include <cuda_fp16.h>
#include <math.h>
#include <stdint.h>

#define NN 100000
#define EE 3200000
#define HID 128
#define NCLS 40
#define MTILES 782   // ceil(100000/128)
#define KP 40        // padded SMEM row length (halves)

// ---------------- scratch (device globals; no allocation) ----------------
__device__ int g_deg[NN];
__device__ int g_rowstart[NN];
__device__ int g_cursor[NN];
__device__ int g_excl[NN];
__device__ int g_bsum[128];
__device__ int g_csrcol[EE];
__device__ __half g_bufA[(size_t)NN * HID];    // Pa (self-projection, fp16)
__device__ __half g_bufB[(size_t)NN * HID];    // Pb (neighbor-projection, fp16)
__device__ __half g_h1[(size_t)NN * HID];      // layer-1 activations (fp16)
__device__ __half g_h2[(size_t)NN * HID];      // layer-2 activations (fp16)

__device__ __forceinline__ uint32_t h2bits(float a, float b) {
    __half2 h = __floats2half2_rn(a, b);
    return *(uint32_t*)&h;
}

__device__ __forceinline__ void mma_f16(float* c, const uint32_t* a, const uint32_t* b) {
    asm volatile(
        "mma.sync.aligned.m16n8k16.row.col.f32.f16.f16.f32 "
        "{%0,%1,%2,%3}, {%4,%5,%6,%7}, {%8,%9}, {%0,%1,%2,%3};"
        : "+f"(c[0]), "+f"(c[1]), "+f"(c[2]), "+f"(c[3])
        : "r"(a[0]), "r"(a[1]), "r"(a[2]), "r"(a[3]), "r"(b[0]), "r"(b[1]));
}

// ---------------- CSR build ----------------
__global__ void k_zero() {
    int i = blockIdx.x * blockDim.x + threadIdx.x;
    if (i < NN) g_deg[i] = 0;
}
__global__ void k_hist(const int* __restrict__ rows) {
    int i = blockIdx.x * blockDim.x + threadIdx.x;
    if (i < EE) atomicAdd(&g_deg[rows[i]], 1);
}
__global__ void k_scan1() {
    __shared__ int s[1024];
    int gid = blockIdx.x * 1024 + threadIdx.x;
    int v = (gid < NN) ? g_deg[gid] : 0;
    s[threadIdx.x] = v;
    __syncthreads();
    #pragma unroll
    for (int off = 1; off < 1024; off <<= 1) {
        int t = (threadIdx.x >= off) ? s[threadIdx.x - off] : 0;
        __syncthreads();
        s[threadIdx.x] += t;
        __syncthreads();
    }
    if (gid < NN) g_excl[gid] = s[threadIdx.x] - v;
    if (threadIdx.x == 1023) g_bsum[blockIdx.x] = s[1023];
}
__global__ void k_scan2(int nb) {
    __shared__ int ws[4];
    int t = threadIdx.x;           // 128 threads
    int lane = t & 31, w = t >> 5;
    int v = (t < nb) ? g_bsum[t] : 0;
    int x = v;
    #pragma unroll
    for (int off = 1; off < 32; off <<= 1) {
        int y = __shfl_up_sync(0xffffffffu, x, off);
        if (lane >= off) x += y;
    }
    if (lane == 31) ws[w] = x;
    __syncthreads();
    int add = 0;
    for (int i = 0; i < w; i++) add += ws[i];
    if (t < nb) g_bsum[t] = x - v + add;   // exclusive scan of block sums
}
__global__ void k_scan3() {
    int gid = blockIdx.x * blockDim.x + threadIdx.x;
    if (gid < NN) {
        int rs = g_excl[gid] + g_bsum[gid >> 10];
        g_rowstart[gid] = rs;
        g_cursor[gid] = rs;
    }
}
__global__ void k_scatter(const int* __restrict__ rows, const int* __restrict__ cols) {
    int i = blockIdx.x * blockDim.x + threadIdx.x;
    if (i < EE) {
        int r = rows[i];
        int p = atomicAdd(&g_cursor[r], 1);
        g_csrcol[p] = cols[i];
    }
}

// ---------------- fp16 mma GEMM (fp32 accumulate) ----------------
// Block tile 128x128, 256 threads = 8 warps (4m x 2n), warp tile 32x64 via m16n8k16.
// blockIdx.y = 0 -> Pa = A @ Wa^T; 1 -> Pb = A @ Wb^T. Both fp16 out.
// Double-buffered half SMEM (16-k chunks), [m][k]-major with 40-half padded rows.
template <int K, int LAYER>
__global__ void __launch_bounds__(256, 2) k_gemm_mma(const float* __restrict__ xin,
                                                     const float* __restrict__ W) {
    __shared__ __half As[2][128][KP];
    __shared__ __half Bs[2][128][KP];

    const int KW = 2 * K;
    const int koff = blockIdx.y * K;
    const int mbase = blockIdx.x * 128;

    const int tid = threadIdx.x;
    const int w = tid >> 5;
    const int lane = tid & 31;
    const int wm = w & 3;
    const int wn = w >> 2;
    const int gid = lane >> 2;   // 0..7
    const int tq = lane & 3;     // 0..3

    const int lrow = tid >> 1;        // 0..127 (stage row)
    const int kb = (tid & 1) * 8;     // half-offset within 16-k chunk

    float c[2][8][4];
    #pragma unroll
    for (int i = 0; i < 2; i++)
        #pragma unroll
        for (int j = 0; j < 8; j++)
            #pragma unroll
            for (int q = 0; q < 4; q++) c[i][j][q] = 0.f;

    const int mload = min(mbase + lrow, NN - 1);
    uint32_t ra[4], rb[4];   // 8 halves each, packed half2

    auto ldg_chunk = [&](int kc) {
        if (LAYER == 1) {
            const float* src = &xin[(size_t)mload * K + kc + kb];
            float4 v0 = *(const float4*)(src);
            float4 v1 = *(const float4*)(src + 4);
            ra[0] = h2bits(v0.x, v0.y);
            ra[1] = h2bits(v0.z, v0.w);
            ra[2] = h2bits(v1.x, v1.y);
            ra[3] = h2bits(v1.z, v1.w);
        } else {
            uint4 raw = *(const uint4*)&g_h1[(size_t)mload * K + kc + kb];
            ra[0] = raw.x; ra[1] = raw.y; ra[2] = raw.z; ra[3] = raw.w;
        }
        const float* wsrc = &W[(size_t)lrow * KW + koff + kc + kb];
        float4 b0 = *(const float4*)(wsrc);
        float4 b1 = *(const float4*)(wsrc + 4);
        rb[0] = h2bits(b0.x, b0.y);
        rb[1] = h2bits(b0.z, b0.w);
        rb[2] = h2bits(b1.x, b1.y);
        rb[3] = h2bits(b1.z, b1.w);
    };
    auto sts_chunk = [&](int buf) {
        *(uint4*)&As[buf][lrow][kb] = make_uint4(ra[0], ra[1], ra[2], ra[3]);
        *(uint4*)&Bs[buf][lrow][kb] = make_uint4(rb[0], rb[1], rb[2], rb[3]);
    };
    auto compute = [&](int buf) {
        uint32_t a[2][4];
        #pragma unroll
        for (int mt = 0; mt < 2; mt++) {
            int rbv = wm * 32 + mt * 16;
            a[mt][0] = *(const uint32_t*)&As[buf][rbv + gid][2 * tq];
            a[mt][1] = *(const uint32_t*)&As[buf][rbv + gid + 8][2 * tq];
            a[mt][2] = *(const uint32_t*)&As[buf][rbv + gid][2 * tq + 8];
            a[mt][3] = *(const uint32_t*)&As[buf][rbv + gid + 8][2 * tq + 8];
        }
        #pragma unroll
        for (int nt = 0; nt < 8; nt++) {
            int nb = wn * 64 + nt * 8;
            uint32_t b[2];
            b[0] = *(const uint32_t*)&Bs[buf][nb + gid][2 * tq];
            b[1] = *(const uint32_t*)&Bs[buf][nb + gid][2 * tq + 8];
            mma_f16(c[0][nt], a[0], b);
            mma_f16(c[1][nt], a[1], b);
        }
    };

    constexpr int NCH = K / 16;
    ldg_chunk(0);
    sts_chunk(0);
    __syncthreads();
    for (int ch = 0; ch < NCH; ch++) {
        if (ch + 1 < NCH) ldg_chunk((ch + 1) * 16);   // LDG in flight during MMAs
        compute(ch & 1);
        if (ch + 1 < NCH) sts_chunk((ch + 1) & 1);
        __syncthreads();
    }

    __half* out = blockIdx.y ? g_bufB : g_bufA;
    #pragma unroll
    for (int mt = 0; mt < 2; mt++) {
        #pragma unroll
        for (int nt = 0; nt < 8; nt++) {
            int row = mbase + wm * 32 + mt * 16 + gid;
            int col = wn * 64 + nt * 8 + 2 * tq;
            if (row < NN)
                *(__half2*)&out[(size_t)row * HID + col] =
                    __floats2half2_rn(c[mt][nt][0], c[mt][nt][1]);
            if (row + 8 < NN)
                *(__half2*)&out[(size_t)(row + 8) * HID + col] =
                    __floats2half2_rn(c[mt][nt][2], c[mt][nt][3]);
        }
    }
}

// ---------------- SpMM fused: h = relu(Pa + agg(Pb)/(deg+1)), warp per node ----------------
// Two edges per warp iteration: lanes 0-15 cover edge j (16 x uint4 = 256B row),
// lanes 16-31 cover edge j+1. Final shfl-down-16 combine, lanes 0-15 store.
template <int ROUND>
__global__ void __launch_bounds__(256) k_spmm() {
    const int tid = threadIdx.x;
    const int w = tid >> 5, lane = tid & 31;
    const int n = blockIdx.x * 8 + w;
    if (n >= NN) return;

    const int e = lane >> 4;     // which edge of the pair (0/1)
    const int fl = lane & 15;    // feature block 0..15 (8 halves each)

    const int d = g_deg[n];
    const int s = g_rowstart[n];

    float acc[8];
    #pragma unroll
    for (int i = 0; i < 8; i++) acc[i] = 0.f;

    for (int base = 0; base < d; base += 32) {
        int rem = d - base;
        int cj = (lane < rem) ? g_csrcol[s + base + lane] : 0;
        int cnt = min(32, rem);
        #pragma unroll 4
        for (int j = 0; j < cnt; j += 2) {
            int col = __shfl_sync(0xffffffffu, cj, j + e);
            uint4 v = *(const uint4*)&g_bufB[(size_t)col * HID + fl * 8];
            if (j + e < cnt) {
                float2 f0 = __half22float2(*(__half2*)&v.x);
                float2 f1 = __half22float2(*(__half2*)&v.y);
                float2 f2 = __half22float2(*(__half2*)&v.z);
                float2 f3 = __half22float2(*(__half2*)&v.w);
                acc[0] += f0.x; acc[1] += f0.y;
                acc[2] += f1.x; acc[3] += f1.y;
                acc[4] += f2.x; acc[5] += f2.y;
                acc[6] += f3.x; acc[7] += f3.y;
            }
        }
    }

    // combine odd-edge partials (lanes 16-31) into lanes 0-15
    #pragma unroll
    for (int i = 0; i < 8; i++)
        acc[i] += __shfl_down_sync(0xffffffffu, acc[i], 16);

    if (e == 0) {
        const float inv = 1.f / ((float)d + 1.0f);
        uint4 pa = *(const uint4*)&g_bufA[(size_t)n * HID + fl * 8];
        float2 p0 = __half22float2(*(__half2*)&pa.x);
        float2 p1 = __half22float2(*(__half2*)&pa.y);
        float2 p2 = __half22float2(*(__half2*)&pa.z);
        float2 p3 = __half22float2(*(__half2*)&pa.w);
        float r0 = fmaxf(p0.x + acc[0] * inv, 0.f);
        float r1 = fmaxf(p0.y + acc[1] * inv, 0.f);
        float r2 = fmaxf(p1.x + acc[2] * inv, 0.f);
        float r3 = fmaxf(p1.y + acc[3] * inv, 0.f);
        float r4 = fmaxf(p2.x + acc[4] * inv, 0.f);
        float r5 = fmaxf(p2.y + acc[5] * inv, 0.f);
        float r6 = fmaxf(p3.x + acc[6] * inv, 0.f);
        float r7 = fmaxf(p3.y + acc[7] * inv, 0.f);

        __half* out = (ROUND == 1) ? g_h1 : g_h2;
        uint4 o;
        *(__half2*)&o.x = __floats2half2_rn(r0, r1);
        *(__half2*)&o.y = __floats2half2_rn(r2, r3);
        *(__half2*)&o.z = __floats2half2_rn(r4, r5);
        *(__half2*)&o.w = __floats2half2_rn(r6, r7);
        *(uint4*)&out[(size_t)n * HID + fl * 8] = o;
    }
}

// ---------------- MLP + log_softmax: persistent, one warp per node ----------------
#define MLP_BLOCKS 592
__global__ void __launch_bounds__(256) k_mlp(const float* __restrict__ Wm,
                                             const float* __restrict__ bias,
                                             float* __restrict__ out) {
    __shared__ float sW[NCLS * 129];
    __shared__ float sb[NCLS];
    __shared__ float sh[8][128];

    int tid = threadIdx.x;
    for (int idx = tid; idx < NCLS * 128; idx += 256) {
        int c = idx >> 7, k = idx & 127;
        sW[c * 129 + k] = Wm[idx];
    }
    if (tid < NCLS) sb[tid] = bias[tid];
    __syncthreads();

    int warp = tid >> 5, lane = tid & 31;
    const int NGRP = NN / 8;   // 12500

    for (int g = blockIdx.x; g < NGRP; g += MLP_BLOCKS) {
        int n = g * 8 + warp;

        {
            uint2 raw = *(const uint2*)&g_h2[(size_t)n * 128 + lane * 4];
            float2 f0 = __half22float2(*(__half2*)&raw.x);
            float2 f1 = __half22float2(*(__half2*)&raw.y);
            sh[warp][lane * 4 + 0] = f0.x;
            sh[warp][lane * 4 + 1] = f0.y;
            sh[warp][lane * 4 + 2] = f1.x;
            sh[warp][lane * 4 + 3] = f1.y;
        }
        __syncwarp();

        float v1 = sb[lane];
        float v2 = (lane < 8) ? sb[lane + 32] : -1e30f;

        const float* swr1 = &sW[lane * 129];
        #pragma unroll 8
        for (int k = 0; k < 128; k++) v1 += sh[warp][k] * swr1[k];
        if (lane < 8) {
            const float* swr2 = &sW[(lane + 32) * 129];
            #pragma unroll 8
            for (int k = 0; k < 128; k++) v2 += sh[warp][k] * swr2[k];
        }

        float mx = fmaxf(v1, v2);
        #pragma unroll
        for (int o = 16; o; o >>= 1) mx = fmaxf(mx, __shfl_xor_sync(0xffffffffu, mx, o));
        float s = expf(v1 - mx) + ((lane < 8) ? expf(v2 - mx) : 0.f);
        #pragma unroll
        for (int o = 16; o; o >>= 1) s += __shfl_xor_sync(0xffffffffu, s, o);
        float lg = logf(s);

        out[(size_t)n * NCLS + lane] = v1 - mx - lg;
        if (lane < 8) out[(size_t)n * NCLS + lane + 32] = v2 - mx - lg;
        __syncwarp();
    }
}

// ---------------- launch ----------------
extern "C" void kernel_launch(void* const* d_in, const int* in_sizes, int n_in,
                              void* d_out, int out_size) {
    const float* x  = (const float*)d_in[0];
    const float* W1 = (const float*)d_in[1];
    const float* W2 = (const float*)d_in[2];
    const float* mW = (const float*)d_in[3];
    const float* mb = (const float*)d_in[4];
    const int*   er = (const int*)d_in[5];
    const int*   ec = (const int*)d_in[6];
    float* out = (float*)d_out;

    // CSR build
    k_zero<<<(NN + 255) / 256, 256>>>();
    k_hist<<<(EE + 255) / 256, 256>>>(er);
    k_scan1<<<(NN + 1023) / 1024, 1024>>>();
    k_scan2<<<1, 128>>>((NN + 1023) / 1024);
    k_scan3<<<(NN + 255) / 256, 256>>>();
    k_scatter<<<(EE + 255) / 256, 256>>>(er, ec);

    // Layer 1: Pa = x@Wa^T, Pb = x@Wb^T (fp16), then h1 = relu(Pa + agg(Pb)/(deg+1))
    k_gemm_mma<256, 1><<<dim3(MTILES, 2), 256>>>(x, W1);
    k_spmm<1><<<(NN + 7) / 8, 256>>>();
    // Layer 2
    k_gemm_mma<128, 2><<<dim3(MTILES, 2), 256>>>(x, W2);
    k_spmm<2><<<(NN + 7) / 8, 256>>>();
    // Head
    k_mlp<<<MLP_BLOCKS, 256>>>(mW, mb, out);
}

// round 12
// speedup vs baseline: 1.0059x; 1.0059x over previous
#include <cuda_runtime.h>
#include <cuda_fp16.h>
#include <math.h>
#include <stdint.h>

#define NN 100000
#define EE 3200000
#define HID 128
#define NCLS 40
#define MTILES 782   // ceil(100000/128)
#define KP 40        // padded SMEM row length (halves)
#define HB 1024      // histogram blocks fused into GEMM1 launch

// ---------------- scratch (device globals; no allocation) ----------------
__device__ int g_deg[NN];
__device__ int g_rowstart[NN];
__device__ int g_cursor[NN];
__device__ int g_excl[NN];
__device__ int g_bsum[128];
__device__ int g_csrcol[EE];
__device__ __half g_bufA[(size_t)NN * HID];    // Pa (self-projection, fp16)
__device__ __half g_bufB[(size_t)NN * HID];    // Pb (neighbor-projection, fp16)
__device__ __half g_h1[(size_t)NN * HID];      // layer-1 activations (fp16)
__device__ __half g_h2[(size_t)NN * HID];      // layer-2 activations (fp16)

__device__ __forceinline__ uint32_t h2bits(float a, float b) {
    __half2 h = __floats2half2_rn(a, b);
    return *(uint32_t*)&h;
}

__device__ __forceinline__ void mma_f16(float* c, const uint32_t* a, const uint32_t* b) {
    asm volatile(
        "mma.sync.aligned.m16n8k16.row.col.f32.f16.f16.f32 "
        "{%0,%1,%2,%3}, {%4,%5,%6,%7}, {%8,%9}, {%0,%1,%2,%3};"
        : "+f"(c[0]), "+f"(c[1]), "+f"(c[2]), "+f"(c[3])
        : "r"(a[0]), "r"(a[1]), "r"(a[2]), "r"(a[3]), "r"(b[0]), "r"(b[1]));
}

// ---------------- CSR build ----------------
__global__ void k_zero() {
    int i = blockIdx.x * blockDim.x + threadIdx.x;
    if (i < NN) g_deg[i] = 0;
}
__global__ void k_scan1() {
    __shared__ int s[1024];
    int gid = blockIdx.x * 1024 + threadIdx.x;
    int v = (gid < NN) ? g_deg[gid] : 0;
    s[threadIdx.x] = v;
    __syncthreads();
    #pragma unroll
    for (int off = 1; off < 1024; off <<= 1) {
        int t = (threadIdx.x >= off) ? s[threadIdx.x - off] : 0;
        __syncthreads();
        s[threadIdx.x] += t;
        __syncthreads();
    }
    if (gid < NN) g_excl[gid] = s[threadIdx.x] - v;
    if (threadIdx.x == 1023) g_bsum[blockIdx.x] = s[1023];
}
__global__ void k_scan2(int nb) {
    __shared__ int ws[4];
    int t = threadIdx.x;           // 128 threads
    int lane = t & 31, w = t >> 5;
    int v = (t < nb) ? g_bsum[t] : 0;
    int x = v;
    #pragma unroll
    for (int off = 1; off < 32; off <<= 1) {
        int y = __shfl_up_sync(0xffffffffu, x, off);
        if (lane >= off) x += y;
    }
    if (lane == 31) ws[w] = x;
    __syncthreads();
    int add = 0;
    for (int i = 0; i < w; i++) add += ws[i];
    if (t < nb) g_bsum[t] = x - v + add;   // exclusive scan of block sums
}
__global__ void k_scan3() {
    int gid = blockIdx.x * blockDim.x + threadIdx.x;
    if (gid < NN) {
        int rs = g_excl[gid] + g_bsum[gid >> 10];
        g_rowstart[gid] = rs;
        g_cursor[gid] = rs;
    }
}
__global__ void k_scatter(const int* __restrict__ rows, const int* __restrict__ cols) {
    int i = blockIdx.x * blockDim.x + threadIdx.x;
    if (i < EE) {
        int r = rows[i];
        int p = atomicAdd(&g_cursor[r], 1);
        g_csrcol[p] = cols[i];
    }
}

// ---------------- fp16 mma GEMM (fp32 accumulate), optional fused edge-hist ----------------
// 1D grid: blocks [0, hb) run the edge histogram (grid-stride); blocks [hb, hb+2*MTILES)
// run GEMM tiles (first MTILES -> Pa half, next MTILES -> Pb half).
// Block tile 128x128, 256 threads = 8 warps (4m x 2n), warp tile 32x64 via m16n8k16.
// Double-buffered half SMEM (16-k chunks), [m][k]-major with 40-half padded rows.
template <int K, int LAYER, int HBN>
__global__ void __launch_bounds__(256, 2) k_gemm_mma(const float* __restrict__ xin,
                                                     const float* __restrict__ W,
                                                     const int* __restrict__ er) {
    __shared__ __half As[2][128][KP];
    __shared__ __half Bs[2][128][KP];

    if (HBN > 0 && blockIdx.x < HBN) {
        // fused histogram: overlaps with GEMM waves
        for (int i = blockIdx.x * 256 + threadIdx.x; i < EE; i += HBN * 256)
            atomicAdd(&g_deg[er[i]], 1);
        return;
    }

    const int bid = blockIdx.x - HBN;
    const int my = (bid >= MTILES) ? 1 : 0;
    const int mbase = (bid - my * MTILES) * 128;
    const int KW = 2 * K;
    const int koff = my * K;

    const int tid = threadIdx.x;
    const int w = tid >> 5;
    const int lane = tid & 31;
    const int wm = w & 3;
    const int wn = w >> 2;
    const int gid = lane >> 2;   // 0..7
    const int tq = lane & 3;     // 0..3

    const int lrow = tid >> 1;        // 0..127 (stage row)
    const int kb = (tid & 1) * 8;     // half-offset within 16-k chunk

    float c[2][8][4];
    #pragma unroll
    for (int i = 0; i < 2; i++)
        #pragma unroll
        for (int j = 0; j < 8; j++)
            #pragma unroll
            for (int q = 0; q < 4; q++) c[i][j][q] = 0.f;

    const int mload = min(mbase + lrow, NN - 1);
    uint32_t ra[4], rb[4];   // 8 halves each, packed half2

    auto ldg_chunk = [&](int kc) {
        if (LAYER == 1) {
            const float* src = &xin[(size_t)mload * K + kc + kb];
            float4 v0 = *(const float4*)(src);
            float4 v1 = *(const float4*)(src + 4);
            ra[0] = h2bits(v0.x, v0.y);
            ra[1] = h2bits(v0.z, v0.w);
            ra[2] = h2bits(v1.x, v1.y);
            ra[3] = h2bits(v1.z, v1.w);
        } else {
            uint4 raw = *(const uint4*)&g_h1[(size_t)mload * K + kc + kb];
            ra[0] = raw.x; ra[1] = raw.y; ra[2] = raw.z; ra[3] = raw.w;
        }
        const float* wsrc = &W[(size_t)lrow * KW + koff + kc + kb];
        float4 b0 = *(const float4*)(wsrc);
        float4 b1 = *(const float4*)(wsrc + 4);
        rb[0] = h2bits(b0.x, b0.y);
        rb[1] = h2bits(b0.z, b0.w);
        rb[2] = h2bits(b1.x, b1.y);
        rb[3] = h2bits(b1.z, b1.w);
    };
    auto sts_chunk = [&](int buf) {
        *(uint4*)&As[buf][lrow][kb] = make_uint4(ra[0], ra[1], ra[2], ra[3]);
        *(uint4*)&Bs[buf][lrow][kb] = make_uint4(rb[0], rb[1], rb[2], rb[3]);
    };
    auto compute = [&](int buf) {
        uint32_t a[2][4];
        #pragma unroll
        for (int mt = 0; mt < 2; mt++) {
            int rbv = wm * 32 + mt * 16;
            a[mt][0] = *(const uint32_t*)&As[buf][rbv + gid][2 * tq];
            a[mt][1] = *(const uint32_t*)&As[buf][rbv + gid + 8][2 * tq];
            a[mt][2] = *(const uint32_t*)&As[buf][rbv + gid][2 * tq + 8];
            a[mt][3] = *(const uint32_t*)&As[buf][rbv + gid + 8][2 * tq + 8];
        }
        #pragma unroll
        for (int nt = 0; nt < 8; nt++) {
            int nb = wn * 64 + nt * 8;
            uint32_t b[2];
            b[0] = *(const uint32_t*)&Bs[buf][nb + gid][2 * tq];
            b[1] = *(const uint32_t*)&Bs[buf][nb + gid][2 * tq + 8];
            mma_f16(c[0][nt], a[0], b);
            mma_f16(c[1][nt], a[1], b);
        }
    };

    constexpr int NCH = K / 16;
    ldg_chunk(0);
    sts_chunk(0);
    __syncthreads();
    for (int ch = 0; ch < NCH; ch++) {
        if (ch + 1 < NCH) ldg_chunk((ch + 1) * 16);   // LDG in flight during MMAs
        compute(ch & 1);
        if (ch + 1 < NCH) sts_chunk((ch + 1) & 1);
        __syncthreads();
    }

    __half* out = my ? g_bufB : g_bufA;
    #pragma unroll
    for (int mt = 0; mt < 2; mt++) {
        #pragma unroll
        for (int nt = 0; nt < 8; nt++) {
            int row = mbase + wm * 32 + mt * 16 + gid;
            int col = wn * 64 + nt * 8 + 2 * tq;
            if (row < NN)
                *(__half2*)&out[(size_t)row * HID + col] =
                    __floats2half2_rn(c[mt][nt][0], c[mt][nt][1]);
            if (row + 8 < NN)
                *(__half2*)&out[(size_t)(row + 8) * HID + col] =
                    __floats2half2_rn(c[mt][nt][2], c[mt][nt][3]);
        }
    }
}

// ---------------- SpMM fused: h = relu(Pa + agg(Pb)/(deg+1)), warp per node ----------------
// (R10-proven form: each lane owns 4 features = 8B; one 256B row per warp access)
template <int ROUND>
__global__ void __launch_bounds__(256) k_spmm() {
    const int tid = threadIdx.x;
    const int w = tid >> 5, lane = tid & 31;
    const int n = blockIdx.x * 8 + w;
    if (n >= NN) return;

    const int d = g_deg[n];
    const int s = g_rowstart[n];

    float acc0 = 0.f, acc1 = 0.f, acc2 = 0.f, acc3 = 0.f;

    for (int base = 0; base < d; base += 32) {
        int rem = d - base;
        int cj = (lane < rem) ? g_csrcol[s + base + lane] : 0;
        int cnt = min(32, rem);
        #pragma unroll 4
        for (int j = 0; j < cnt; j++) {
            int col = __shfl_sync(0xffffffffu, cj, j);
            uint2 v = *(const uint2*)&g_bufB[(size_t)col * HID + lane * 4];
            float2 f0 = __half22float2(*(__half2*)&v.x);
            float2 f1 = __half22float2(*(__half2*)&v.y);
            acc0 += f0.x; acc1 += f0.y;
            acc2 += f1.x; acc3 += f1.y;
        }
    }

    const float inv = 1.f / ((float)d + 1.0f);
    uint2 pa2 = *(const uint2*)&g_bufA[(size_t)n * HID + lane * 4];
    float2 p0 = __half22float2(*(__half2*)&pa2.x);
    float2 p1 = __half22float2(*(__half2*)&pa2.y);
    float r0 = fmaxf(p0.x + acc0 * inv, 0.f);
    float r1 = fmaxf(p0.y + acc1 * inv, 0.f);
    float r2 = fmaxf(p1.x + acc2 * inv, 0.f);
    float r3 = fmaxf(p1.y + acc3 * inv, 0.f);

    __half* out = (ROUND == 1) ? g_h1 : g_h2;
    uint2 o;
    *(__half2*)&o.x = __floats2half2_rn(r0, r1);
    *(__half2*)&o.y = __floats2half2_rn(r2, r3);
    *(uint2*)&out[(size_t)n * HID + lane * 4] = o;
}

// ---------------- MLP + log_softmax: persistent, one warp per node ----------------
#define MLP_BLOCKS 592
__global__ void __launch_bounds__(256) k_mlp(const float* __restrict__ Wm,
                                             const float* __restrict__ bias,
                                             float* __restrict__ out) {
    __shared__ float sW[NCLS * 129];
    __shared__ float sb[NCLS];
    __shared__ float sh[8][128];

    int tid = threadIdx.x;
    for (int idx = tid; idx < NCLS * 128; idx += 256) {
        int c = idx >> 7, k = idx & 127;
        sW[c * 129 + k] = Wm[idx];
    }
    if (tid < NCLS) sb[tid] = bias[tid];
    __syncthreads();

    int warp = tid >> 5, lane = tid & 31;
    const int NGRP = NN / 8;   // 12500

    for (int g = blockIdx.x; g < NGRP; g += MLP_BLOCKS) {
        int n = g * 8 + warp;

        {
            uint2 raw = *(const uint2*)&g_h2[(size_t)n * 128 + lane * 4];
            float2 f0 = __half22float2(*(__half2*)&raw.x);
            float2 f1 = __half22float2(*(__half2*)&raw.y);
            sh[warp][lane * 4 + 0] = f0.x;
            sh[warp][lane * 4 + 1] = f0.y;
            sh[warp][lane * 4 + 2] = f1.x;
            sh[warp][lane * 4 + 3] = f1.y;
        }
        __syncwarp();

        float v1 = sb[lane];
        float v2 = (lane < 8) ? sb[lane + 32] : -1e30f;

        const float* swr1 = &sW[lane * 129];
        #pragma unroll 8
        for (int k = 0; k < 128; k++) v1 += sh[warp][k] * swr1[k];
        if (lane < 8) {
            const float* swr2 = &sW[(lane + 32) * 129];
            #pragma unroll 8
            for (int k = 0; k < 128; k++) v2 += sh[warp][k] * swr2[k];
        }

        float mx = fmaxf(v1, v2);
        #pragma unroll
        for (int o = 16; o; o >>= 1) mx = fmaxf(mx, __shfl_xor_sync(0xffffffffu, mx, o));
        float s = expf(v1 - mx) + ((lane < 8) ? expf(v2 - mx) : 0.f);
        #pragma unroll
        for (int o = 16; o; o >>= 1) s += __shfl_xor_sync(0xffffffffu, s, o);
        float lg = logf(s);

        out[(size_t)n * NCLS + lane] = v1 - mx - lg;
        if (lane < 8) out[(size_t)n * NCLS + lane + 32] = v2 - mx - lg;
        __syncwarp();
    }
}

// ---------------- launch ----------------
extern "C" void kernel_launch(void* const* d_in, const int* in_sizes, int n_in,
                              void* d_out, int out_size) {
    const float* x  = (const float*)d_in[0];
    const float* W1 = (const float*)d_in[1];
    const float* W2 = (const float*)d_in[2];
    const float* mW = (const float*)d_in[3];
    const float* mb = (const float*)d_in[4];
    const int*   er = (const int*)d_in[5];
    const int*   ec = (const int*)d_in[6];
    float* out = (float*)d_out;

    // zero degree counters, then GEMM1 fused with edge histogram (hist blocks first)
    k_zero<<<(NN + 255) / 256, 256>>>();
    k_gemm_mma<256, 1, HB><<<HB + 2 * MTILES, 256>>>(x, W1, er);

    // scan + scatter (CSR)
    k_scan1<<<(NN + 1023) / 1024, 1024>>>();
    k_scan2<<<1, 128>>>((NN + 1023) / 1024);
    k_scan3<<<(NN + 255) / 256, 256>>>();
    k_scatter<<<(EE + 255) / 256, 256>>>(er, ec);

    // Layer 1 aggregate: h1 = relu(Pa + agg(Pb)/(deg+1))
    k_spmm<1><<<(NN + 7) / 8, 256>>>();
    // Layer 2
    k_gemm_mma<128, 2, 0><<<2 * MTILES, 256>>>(x, W2, er);
    k_spmm<2><<<(NN + 7) / 8, 256>>>();
    // Head
    k_mlp<<<MLP_BLOCKS, 256>>>(mW, mb, out);
}

// round 13
// speedup vs baseline: 1.0346x; 1.0286x over previous
#include <cuda_runtime.h>
#include <cuda_fp16.h>
#include <math.h>
#include <stdint.h>

#define NN 100000
#define EE 3200000
#define HID 128
#define NCLS 40
#define MTILES 782   // ceil(100000/128)
#define KP 40        // padded SMEM row length (halves)

// ---------------- scratch (device globals; no allocation) ----------------
// g_deg is zero-initialized at module load and re-zeroed at the end of every
// call (in k_mlp, after all readers) so k_hist can accumulate directly.
__device__ int g_deg[NN];
__device__ int g_rowstart[NN];
__device__ int g_cursor[NN];
__device__ int g_excl[NN];
__device__ int g_bsum[128];
__device__ int g_csrcol[EE];
__device__ __half g_bufA[(size_t)NN * HID];    // Pa (self-projection, fp16)
__device__ __half g_bufB[(size_t)NN * HID];    // Pb (neighbor-projection, fp16)
__device__ __half g_h1[(size_t)NN * HID];      // layer-1 activations (fp16)
__device__ __half g_h2[(size_t)NN * HID];      // layer-2 activations (fp16)

__device__ __forceinline__ uint32_t h2bits(float a, float b) {
    __half2 h = __floats2half2_rn(a, b);
    return *(uint32_t*)&h;
}

__device__ __forceinline__ void mma_f16(float* c, const uint32_t* a, const uint32_t* b) {
    asm volatile(
        "mma.sync.aligned.m16n8k16.row.col.f32.f16.f16.f32 "
        "{%0,%1,%2,%3}, {%4,%5,%6,%7}, {%8,%9}, {%0,%1,%2,%3};"
        : "+f"(c[0]), "+f"(c[1]), "+f"(c[2]), "+f"(c[3])
        : "r"(a[0]), "r"(a[1]), "r"(a[2]), "r"(a[3]), "r"(b[0]), "r"(b[1]));
}

// ---------------- CSR build ----------------
__global__ void k_hist(const int* __restrict__ rows) {
    int i = blockIdx.x * blockDim.x + threadIdx.x;
    if (i < EE) atomicAdd(&g_deg[rows[i]], 1);
}
__global__ void k_scan1() {
    __shared__ int s[1024];
    int gid = blockIdx.x * 1024 + threadIdx.x;
    int v = (gid < NN) ? g_deg[gid] : 0;
    s[threadIdx.x] = v;
    __syncthreads();
    #pragma unroll
    for (int off = 1; off < 1024; off <<= 1) {
        int t = (threadIdx.x >= off) ? s[threadIdx.x - off] : 0;
        __syncthreads();
        s[threadIdx.x] += t;
        __syncthreads();
    }
    if (gid < NN) g_excl[gid] = s[threadIdx.x] - v;
    if (threadIdx.x == 1023) g_bsum[blockIdx.x] = s[1023];
}
__global__ void k_scan2(int nb) {
    __shared__ int ws[4];
    int t = threadIdx.x;           // 128 threads
    int lane = t & 31, w = t >> 5;
    int v = (t < nb) ? g_bsum[t] : 0;
    int x = v;
    #pragma unroll
    for (int off = 1; off < 32; off <<= 1) {
        int y = __shfl_up_sync(0xffffffffu, x, off);
        if (lane >= off) x += y;
    }
    if (lane == 31) ws[w] = x;
    __syncthreads();
    int add = 0;
    for (int i = 0; i < w; i++) add += ws[i];
    if (t < nb) g_bsum[t] = x - v + add;   // exclusive scan of block sums
}
__global__ void k_scan3() {
    int gid = blockIdx.x * blockDim.x + threadIdx.x;
    if (gid < NN) {
        int rs = g_excl[gid] + g_bsum[gid >> 10];
        g_rowstart[gid] = rs;
        g_cursor[gid] = rs;
    }
}
__global__ void k_scatter(const int* __restrict__ rows, const int* __restrict__ cols) {
    int i = blockIdx.x * blockDim.x + threadIdx.x;
    if (i < EE) {
        int r = rows[i];
        int p = atomicAdd(&g_cursor[r], 1);
        g_csrcol[p] = cols[i];
    }
}

// ---------------- fp16 mma GEMM (fp32 accumulate) ----------------
// Block tile 128x128, 256 threads = 8 warps (4m x 2n), warp tile 32x64 via m16n8k16.
// blockIdx.y = 0 -> Pa = A @ Wa^T; 1 -> Pb = A @ Wb^T. Both fp16 out.
// Double-buffered half SMEM (16-k chunks), [m][k]-major with 40-half padded rows.
template <int K, int LAYER>
__global__ void __launch_bounds__(256, 2) k_gemm_mma(const float* __restrict__ xin,
                                                     const float* __restrict__ W) {
    __shared__ __half As[2][128][KP];
    __shared__ __half Bs[2][128][KP];

    const int KW = 2 * K;
    const int koff = blockIdx.y * K;
    const int mbase = blockIdx.x * 128;

    const int tid = threadIdx.x;
    const int w = tid >> 5;
    const int lane = tid & 31;
    const int wm = w & 3;
    const int wn = w >> 2;
    const int gid = lane >> 2;   // 0..7
    const int tq = lane & 3;     // 0..3

    const int lrow = tid >> 1;        // 0..127 (stage row)
    const int kb = (tid & 1) * 8;     // half-offset within 16-k chunk

    float c[2][8][4];
    #pragma unroll
    for (int i = 0; i < 2; i++)
        #pragma unroll
        for (int j = 0; j < 8; j++)
            #pragma unroll
            for (int q = 0; q < 4; q++) c[i][j][q] = 0.f;

    const int mload = min(mbase + lrow, NN - 1);
    uint32_t ra[4], rb[4];   // 8 halves each, packed half2

    auto ldg_chunk = [&](int kc) {
        if (LAYER == 1) {
            const float* src = &xin[(size_t)mload * K + kc + kb];
            float4 v0 = *(const float4*)(src);
            float4 v1 = *(const float4*)(src + 4);
            ra[0] = h2bits(v0.x, v0.y);
            ra[1] = h2bits(v0.z, v0.w);
            ra[2] = h2bits(v1.x, v1.y);
            ra[3] = h2bits(v1.z, v1.w);
        } else {
            uint4 raw = *(const uint4*)&g_h1[(size_t)mload * K + kc + kb];
            ra[0] = raw.x; ra[1] = raw.y; ra[2] = raw.z; ra[3] = raw.w;
        }
        const float* wsrc = &W[(size_t)lrow * KW + koff + kc + kb];
        float4 b0 = *(const float4*)(wsrc);
        float4 b1 = *(const float4*)(wsrc + 4);
        rb[0] = h2bits(b0.x, b0.y);
        rb[1] = h2bits(b0.z, b0.w);
        rb[2] = h2bits(b1.x, b1.y);
        rb[3] = h2bits(b1.z, b1.w);
    };
    auto sts_chunk = [&](int buf) {
        *(uint4*)&As[buf][lrow][kb] = make_uint4(ra[0], ra[1], ra[2], ra[3]);
        *(uint4*)&Bs[buf][lrow][kb] = make_uint4(rb[0], rb[1], rb[2], rb[3]);
    };
    auto compute = [&](int buf) {
        uint32_t a[2][4];
        #pragma unroll
        for (int mt = 0; mt < 2; mt++) {
            int rbv = wm * 32 + mt * 16;
            a[mt][0] = *(const uint32_t*)&As[buf][rbv + gid][2 * tq];
            a[mt][1] = *(const uint32_t*)&As[buf][rbv + gid + 8][2 * tq];
            a[mt][2] = *(const uint32_t*)&As[buf][rbv + gid][2 * tq + 8];
            a[mt][3] = *(const uint32_t*)&As[buf][rbv + gid + 8][2 * tq + 8];
        }
        #pragma unroll
        for (int nt = 0; nt < 8; nt++) {
            int nb = wn * 64 + nt * 8;
            uint32_t b[2];
            b[0] = *(const uint32_t*)&Bs[buf][nb + gid][2 * tq];
            b[1] = *(const uint32_t*)&Bs[buf][nb + gid][2 * tq + 8];
            mma_f16(c[0][nt], a[0], b);
            mma_f16(c[1][nt], a[1], b);
        }
    };

    constexpr int NCH = K / 16;
    ldg_chunk(0);
    sts_chunk(0);
    __syncthreads();
    for (int ch = 0; ch < NCH; ch++) {
        if (ch + 1 < NCH) ldg_chunk((ch + 1) * 16);   // LDG in flight during MMAs
        compute(ch & 1);
        if (ch + 1 < NCH) sts_chunk((ch + 1) & 1);
        __syncthreads();
    }

    __half* out = blockIdx.y ? g_bufB : g_bufA;
    #pragma unroll
    for (int mt = 0; mt < 2; mt++) {
        #pragma unroll
        for (int nt = 0; nt < 8; nt++) {
            int row = mbase + wm * 32 + mt * 16 + gid;
            int col = wn * 64 + nt * 8 + 2 * tq;
            if (row < NN)
                *(__half2*)&out[(size_t)row * HID + col] =
                    __floats2half2_rn(c[mt][nt][0], c[mt][nt][1]);
            if (row + 8 < NN)
                *(__half2*)&out[(size_t)(row + 8) * HID + col] =
                    __floats2half2_rn(c[mt][nt][2], c[mt][nt][3]);
        }
    }
}

// ---------------- SpMM fused: h = relu(Pa + agg(Pb)/(deg+1)), warp per node ----------------
// Each lane owns 4 features (uint2 = 8B); 32 lanes = one 256B fp16 row per edge.
// Inner loop batches 8 independent row-loads into registers before accumulating (MLP=8).
template <int ROUND>
__global__ void __launch_bounds__(256) k_spmm() {
    const int tid = threadIdx.x;
    const int w = tid >> 5, lane = tid & 31;
    const int n = blockIdx.x * 8 + w;
    if (n >= NN) return;

    const int d = g_deg[n];
    const int s = g_rowstart[n];

    float acc0 = 0.f, acc1 = 0.f, acc2 = 0.f, acc3 = 0.f;

    for (int base = 0; base < d; base += 32) {
        int rem = d - base;
        int cj = (lane < rem) ? g_csrcol[s + base + lane] : 0;
        int cnt = min(32, rem);
        int j = 0;
        for (; j + 8 <= cnt; j += 8) {
            uint2 v[8];
            #pragma unroll
            for (int u = 0; u < 8; u++) {
                int col = __shfl_sync(0xffffffffu, cj, j + u);
                v[u] = *(const uint2*)&g_bufB[(size_t)col * HID + lane * 4];
            }
            #pragma unroll
            for (int u = 0; u < 8; u++) {
                float2 f0 = __half22float2(*(__half2*)&v[u].x);
                float2 f1 = __half22float2(*(__half2*)&v[u].y);
                acc0 += f0.x; acc1 += f0.y;
                acc2 += f1.x; acc3 += f1.y;
            }
        }
        for (; j < cnt; j++) {
            int col = __shfl_sync(0xffffffffu, cj, j);
            uint2 v = *(const uint2*)&g_bufB[(size_t)col * HID + lane * 4];
            float2 f0 = __half22float2(*(__half2*)&v.x);
            float2 f1 = __half22float2(*(__half2*)&v.y);
            acc0 += f0.x; acc1 += f0.y;
            acc2 += f1.x; acc3 += f1.y;
        }
    }

    const float inv = 1.f / ((float)d + 1.0f);
    uint2 pa2 = *(const uint2*)&g_bufA[(size_t)n * HID + lane * 4];
    float2 p0 = __half22float2(*(__half2*)&pa2.x);
    float2 p1 = __half22float2(*(__half2*)&pa2.y);
    float r0 = fmaxf(p0.x + acc0 * inv, 0.f);
    float r1 = fmaxf(p0.y + acc1 * inv, 0.f);
    float r2 = fmaxf(p1.x + acc2 * inv, 0.f);
    float r3 = fmaxf(p1.y + acc3 * inv, 0.f);

    __half* out = (ROUND == 1) ? g_h1 : g_h2;
    uint2 o;
    *(__half2*)&o.x = __floats2half2_rn(r0, r1);
    *(__half2*)&o.y = __floats2half2_rn(r2, r3);
    *(uint2*)&out[(size_t)n * HID + lane * 4] = o;
}

// ---------------- MLP + log_softmax: persistent, one warp per node ----------------
// Also re-zeroes g_deg for the next call (all deg readers have finished).
#define MLP_BLOCKS 592
__global__ void __launch_bounds__(256) k_mlp(const float* __restrict__ Wm,
                                             const float* __restrict__ bias,
                                             float* __restrict__ out) {
    __shared__ float sW[NCLS * 129];
    __shared__ float sb[NCLS];
    __shared__ float sh[8][128];

    int tid = threadIdx.x;
    for (int idx = tid; idx < NCLS * 128; idx += 256) {
        int c = idx >> 7, k = idx & 127;
        sW[c * 129 + k] = Wm[idx];
    }
    if (tid < NCLS) sb[tid] = bias[tid];

    // re-zero degree counters for the next call (readers all upstream)
    for (int i = blockIdx.x * 256 + tid; i < NN; i += MLP_BLOCKS * 256)
        g_deg[i] = 0;
    __syncthreads();

    int warp = tid >> 5, lane = tid & 31;
    const int NGRP = NN / 8;   // 12500

    for (int g = blockIdx.x; g < NGRP; g += MLP_BLOCKS) {
        int n = g * 8 + warp;

        {
            uint2 raw = *(const uint2*)&g_h2[(size_t)n * 128 + lane * 4];
            float2 f0 = __half22float2(*(__half2*)&raw.x);
            float2 f1 = __half22float2(*(__half2*)&raw.y);
            sh[warp][lane * 4 + 0] = f0.x;
            sh[warp][lane * 4 + 1] = f0.y;
            sh[warp][lane * 4 + 2] = f1.x;
            sh[warp][lane * 4 + 3] = f1.y;
        }
        __syncwarp();

        float v1 = sb[lane];
        float v2 = (lane < 8) ? sb[lane + 32] : -1e30f;

        const float* swr1 = &sW[lane * 129];
        #pragma unroll 8
        for (int k = 0; k < 128; k++) v1 += sh[warp][k] * swr1[k];
        if (lane < 8) {
            const float* swr2 = &sW[(lane + 32) * 129];
            #pragma unroll 8
            for (int k = 0; k < 128; k++) v2 += sh[warp][k] * swr2[k];
        }

        float mx = fmaxf(v1, v2);
        #pragma unroll
        for (int o = 16; o; o >>= 1) mx = fmaxf(mx, __shfl_xor_sync(0xffffffffu, mx, o));
        float s = expf(v1 - mx) + ((lane < 8) ? expf(v2 - mx) : 0.f);
        #pragma unroll
        for (int o = 16; o; o >>= 1) s += __shfl_xor_sync(0xffffffffu, s, o);
        float lg = logf(s);

        out[(size_t)n * NCLS + lane] = v1 - mx - lg;
        if (lane < 8) out[(size_t)n * NCLS + lane + 32] = v2 - mx - lg;
        __syncwarp();
    }
}

// ---------------- launch ----------------
extern "C" void kernel_launch(void* const* d_in, const int* in_sizes, int n_in,
                              void* d_out, int out_size) {
    const float* x  = (const float*)d_in[0];
    const float* W1 = (const float*)d_in[1];
    const float* W2 = (const float*)d_in[2];
    const float* mW = (const float*)d_in[3];
    const float* mb = (const float*)d_in[4];
    const int*   er = (const int*)d_in[5];
    const int*   ec = (const int*)d_in[6];
    float* out = (float*)d_out;

    // CSR build (g_deg pre-zeroed: .bss init on first call, k_mlp re-zero after)
    k_hist<<<(EE + 255) / 256, 256>>>(er);
    k_scan1<<<(NN + 1023) / 1024, 1024>>>();
    k_scan2<<<1, 128>>>((NN + 1023) / 1024);
    k_scan3<<<(NN + 255) / 256, 256>>>();
    k_scatter<<<(EE + 255) / 256, 256>>>(er, ec);

    // Layer 1: Pa = x@Wa^T, Pb = x@Wb^T (fp16), then h1 = relu(Pa + agg(Pb)/(deg+1))
    k_gemm_mma<256, 1><<<dim3(MTILES, 2), 256>>>(x, W1);
    k_spmm<1><<<(NN + 7) / 8, 256>>>();
    // Layer 2
    k_gemm_mma<128, 2><<<dim3(MTILES, 2), 256>>>(x, W2);
    k_spmm<2><<<(NN + 7) / 8, 256>>>();
    // Head
    k_mlp<<<MLP_BLOCKS, 256>>>(mW, mb, out);
}

// round 14
// speedup vs baseline: 1.0748x; 1.0388x over previous
#include <cuda_runtime.h>
#include <cuda_fp16.h>
#include <math.h>
#include <stdint.h>

#define NN 100000
#define EE 3200000
#define HID 128
#define NCLS 40
#define MTILES 782   // ceil(100000/128)
#define KP 40        // padded SMEM row length (halves)

// ---------------- scratch (device globals; no allocation) ----------------
// g_deg is zero-initialized at module load; each warp re-zeroes its own node's
// counter at the end of the fused spmm2 (after reading it), so every call
// starts from zeros. Deterministic, race-free.
__device__ int g_deg[NN];
__device__ int g_rowstart[NN];
__device__ int g_cursor[NN];
__device__ int g_excl[NN];
__device__ int g_bsum[128];
__device__ int g_csrcol[EE];
__device__ __half g_bufA[(size_t)NN * HID];    // Pa (self-projection, fp16)
__device__ __half g_bufB[(size_t)NN * HID];    // Pb (neighbor-projection, fp16)
__device__ __half g_h1[(size_t)NN * HID];      // layer-1 activations (fp16)

__device__ __forceinline__ uint32_t h2bits(float a, float b) {
    __half2 h = __floats2half2_rn(a, b);
    return *(uint32_t*)&h;
}

__device__ __forceinline__ void mma_f16(float* c, const uint32_t* a, const uint32_t* b) {
    asm volatile(
        "mma.sync.aligned.m16n8k16.row.col.f32.f16.f16.f32 "
        "{%0,%1,%2,%3}, {%4,%5,%6,%7}, {%8,%9}, {%0,%1,%2,%3};"
        : "+f"(c[0]), "+f"(c[1]), "+f"(c[2]), "+f"(c[3])
        : "r"(a[0]), "r"(a[1]), "r"(a[2]), "r"(a[3]), "r"(b[0]), "r"(b[1]));
}

// ---------------- CSR build ----------------
__global__ void k_hist(const int* __restrict__ rows) {
    int i = blockIdx.x * blockDim.x + threadIdx.x;
    if (i < EE) atomicAdd(&g_deg[rows[i]], 1);
}
__global__ void k_scan1() {
    __shared__ int s[1024];
    int gid = blockIdx.x * 1024 + threadIdx.x;
    int v = (gid < NN) ? g_deg[gid] : 0;
    s[threadIdx.x] = v;
    __syncthreads();
    #pragma unroll
    for (int off = 1; off < 1024; off <<= 1) {
        int t = (threadIdx.x >= off) ? s[threadIdx.x - off] : 0;
        __syncthreads();
        s[threadIdx.x] += t;
        __syncthreads();
    }
    if (gid < NN) g_excl[gid] = s[threadIdx.x] - v;
    if (threadIdx.x == 1023) g_bsum[blockIdx.x] = s[1023];
}
__global__ void k_scan2(int nb) {
    __shared__ int ws[4];
    int t = threadIdx.x;           // 128 threads
    int lane = t & 31, w = t >> 5;
    int v = (t < nb) ? g_bsum[t] : 0;
    int x = v;
    #pragma unroll
    for (int off = 1; off < 32; off <<= 1) {
        int y = __shfl_up_sync(0xffffffffu, x, off);
        if (lane >= off) x += y;
    }
    if (lane == 31) ws[w] = x;
    __syncthreads();
    int add = 0;
    for (int i = 0; i < w; i++) add += ws[i];
    if (t < nb) g_bsum[t] = x - v + add;   // exclusive scan of block sums
}
__global__ void k_scan3() {
    int gid = blockIdx.x * blockDim.x + threadIdx.x;
    if (gid < NN) {
        int rs = g_excl[gid] + g_bsum[gid >> 10];
        g_rowstart[gid] = rs;
        g_cursor[gid] = rs;
    }
}
__global__ void k_scatter(const int* __restrict__ rows, const int* __restrict__ cols) {
    int i = blockIdx.x * blockDim.x + threadIdx.x;
    if (i < EE) {
        int r = rows[i];
        int p = atomicAdd(&g_cursor[r], 1);
        g_csrcol[p] = cols[i];
    }
}

// ---------------- fp16 mma GEMM (fp32 accumulate) ----------------
// Block tile 128x128, 256 threads = 8 warps (4m x 2n), warp tile 32x64 via m16n8k16.
// blockIdx.y = 0 -> Pa = A @ Wa^T; 1 -> Pb = A @ Wb^T. Both fp16 out.
// Double-buffered half SMEM (16-k chunks), [m][k]-major with 40-half padded rows.
template <int K, int LAYER>
__global__ void __launch_bounds__(256, 2) k_gemm_mma(const float* __restrict__ xin,
                                                     const float* __restrict__ W) {
    __shared__ __half As[2][128][KP];
    __shared__ __half Bs[2][128][KP];

    const int KW = 2 * K;
    const int koff = blockIdx.y * K;
    const int mbase = blockIdx.x * 128;

    const int tid = threadIdx.x;
    const int w = tid >> 5;
    const int lane = tid & 31;
    const int wm = w & 3;
    const int wn = w >> 2;
    const int gid = lane >> 2;   // 0..7
    const int tq = lane & 3;     // 0..3

    const int lrow = tid >> 1;        // 0..127 (stage row)
    const int kb = (tid & 1) * 8;     // half-offset within 16-k chunk

    float c[2][8][4];
    #pragma unroll
    for (int i = 0; i < 2; i++)
        #pragma unroll
        for (int j = 0; j < 8; j++)
            #pragma unroll
            for (int q = 0; q < 4; q++) c[i][j][q] = 0.f;

    const int mload = min(mbase + lrow, NN - 1);
    uint32_t ra[4], rb[4];   // 8 halves each, packed half2

    auto ldg_chunk = [&](int kc) {
        if (LAYER == 1) {
            const float* src = &xin[(size_t)mload * K + kc + kb];
            float4 v0 = *(const float4*)(src);
            float4 v1 = *(const float4*)(src + 4);
            ra[0] = h2bits(v0.x, v0.y);
            ra[1] = h2bits(v0.z, v0.w);
            ra[2] = h2bits(v1.x, v1.y);
            ra[3] = h2bits(v1.z, v1.w);
        } else {
            uint4 raw = *(const uint4*)&g_h1[(size_t)mload * K + kc + kb];
            ra[0] = raw.x; ra[1] = raw.y; ra[2] = raw.z; ra[3] = raw.w;
        }
        const float* wsrc = &W[(size_t)lrow * KW + koff + kc + kb];
        float4 b0 = *(const float4*)(wsrc);
        float4 b1 = *(const float4*)(wsrc + 4);
        rb[0] = h2bits(b0.x, b0.y);
        rb[1] = h2bits(b0.z, b0.w);
        rb[2] = h2bits(b1.x, b1.y);
        rb[3] = h2bits(b1.z, b1.w);
    };
    auto sts_chunk = [&](int buf) {
        *(uint4*)&As[buf][lrow][kb] = make_uint4(ra[0], ra[1], ra[2], ra[3]);
        *(uint4*)&Bs[buf][lrow][kb] = make_uint4(rb[0], rb[1], rb[2], rb[3]);
    };
    auto compute = [&](int buf) {
        uint32_t a[2][4];
        #pragma unroll
        for (int mt = 0; mt < 2; mt++) {
            int rbv = wm * 32 + mt * 16;
            a[mt][0] = *(const uint32_t*)&As[buf][rbv + gid][2 * tq];
            a[mt][1] = *(const uint32_t*)&As[buf][rbv + gid + 8][2 * tq];
            a[mt][2] = *(const uint32_t*)&As[buf][rbv + gid][2 * tq + 8];
            a[mt][3] = *(const uint32_t*)&As[buf][rbv + gid + 8][2 * tq + 8];
        }
        #pragma unroll
        for (int nt = 0; nt < 8; nt++) {
            int nb = wn * 64 + nt * 8;
            uint32_t b[2];
            b[0] = *(const uint32_t*)&Bs[buf][nb + gid][2 * tq];
            b[1] = *(const uint32_t*)&Bs[buf][nb + gid][2 * tq + 8];
            mma_f16(c[0][nt], a[0], b);
            mma_f16(c[1][nt], a[1], b);
        }
    };

    constexpr int NCH = K / 16;
    ldg_chunk(0);
    sts_chunk(0);
    __syncthreads();
    for (int ch = 0; ch < NCH; ch++) {
        if (ch + 1 < NCH) ldg_chunk((ch + 1) * 16);   // LDG in flight during MMAs
        compute(ch & 1);
        if (ch + 1 < NCH) sts_chunk((ch + 1) & 1);
        __syncthreads();
    }

    __half* out = blockIdx.y ? g_bufB : g_bufA;
    #pragma unroll
    for (int mt = 0; mt < 2; mt++) {
        #pragma unroll
        for (int nt = 0; nt < 8; nt++) {
            int row = mbase + wm * 32 + mt * 16 + gid;
            int col = wn * 64 + nt * 8 + 2 * tq;
            if (row < NN)
                *(__half2*)&out[(size_t)row * HID + col] =
                    __floats2half2_rn(c[mt][nt][0], c[mt][nt][1]);
            if (row + 8 < NN)
                *(__half2*)&out[(size_t)(row + 8) * HID + col] =
                    __floats2half2_rn(c[mt][nt][2], c[mt][nt][3]);
        }
    }
}

// ---------------- SpMM layer 1: h1 = relu(Pa + agg(Pb)/(deg+1)), warp per node ----------------
__global__ void __launch_bounds__(256) k_spmm1() {
    const int tid = threadIdx.x;
    const int w = tid >> 5, lane = tid & 31;
    const int n = blockIdx.x * 8 + w;
    if (n >= NN) return;

    const int d = g_deg[n];
    const int s = g_rowstart[n];

    float acc0 = 0.f, acc1 = 0.f, acc2 = 0.f, acc3 = 0.f;

    for (int base = 0; base < d; base += 32) {
        int rem = d - base;
        int cj = (lane < rem) ? g_csrcol[s + base + lane] : 0;
        int cnt = min(32, rem);
        int j = 0;
        for (; j + 8 <= cnt; j += 8) {
            uint2 v[8];
            #pragma unroll
            for (int u = 0; u < 8; u++) {
                int col = __shfl_sync(0xffffffffu, cj, j + u);
                v[u] = *(const uint2*)&g_bufB[(size_t)col * HID + lane * 4];
            }
            #pragma unroll
            for (int u = 0; u < 8; u++) {
                float2 f0 = __half22float2(*(__half2*)&v[u].x);
                float2 f1 = __half22float2(*(__half2*)&v[u].y);
                acc0 += f0.x; acc1 += f0.y;
                acc2 += f1.x; acc3 += f1.y;
            }
        }
        for (; j < cnt; j++) {
            int col = __shfl_sync(0xffffffffu, cj, j);
            uint2 v = *(const uint2*)&g_bufB[(size_t)col * HID + lane * 4];
            float2 f0 = __half22float2(*(__half2*)&v.x);
            float2 f1 = __half22float2(*(__half2*)&v.y);
            acc0 += f0.x; acc1 += f0.y;
            acc2 += f1.x; acc3 += f1.y;
        }
    }

    const float inv = 1.f / ((float)d + 1.0f);
    uint2 pa2 = *(const uint2*)&g_bufA[(size_t)n * HID + lane * 4];
    float2 p0 = __half22float2(*(__half2*)&pa2.x);
    float2 p1 = __half22float2(*(__half2*)&pa2.y);
    float r0 = fmaxf(p0.x + acc0 * inv, 0.f);
    float r1 = fmaxf(p0.y + acc1 * inv, 0.f);
    float r2 = fmaxf(p1.x + acc2 * inv, 0.f);
    float r3 = fmaxf(p1.y + acc3 * inv, 0.f);

    uint2 o;
    *(__half2*)&o.x = __floats2half2_rn(r0, r1);
    *(__half2*)&o.y = __floats2half2_rn(r2, r3);
    *(uint2*)&g_h1[(size_t)n * HID + lane * 4] = o;
}

// ---------------- SpMM layer 2 FUSED with MLP + log_softmax ----------------
// Warp per node. After the gather, each warp holds h2[n] across lanes (4/lane);
// it writes the row to SMEM and computes the 40-class head directly.
// Also re-zeroes this node's g_deg entry (after reading) for the next call.
__global__ void __launch_bounds__(256) k_spmm2_mlp(const float* __restrict__ Wm,
                                                   const float* __restrict__ bias,
                                                   float* __restrict__ out) {
    __shared__ float sW[NCLS * 129];
    __shared__ float sb[NCLS];
    __shared__ float sh[8][128];

    const int tid = threadIdx.x;
    // stage MLP weights once per block (overlaps with gather issue below)
    for (int idx = tid; idx < NCLS * 128; idx += 256) {
        int cc = idx >> 7, k = idx & 127;
        sW[cc * 129 + k] = Wm[idx];
    }
    if (tid < NCLS) sb[tid] = bias[tid];

    const int w = tid >> 5, lane = tid & 31;
    const int n = blockIdx.x * 8 + w;   // NN divisible by 8: no stragglers

    const int d = g_deg[n];
    const int s = g_rowstart[n];

    float acc0 = 0.f, acc1 = 0.f, acc2 = 0.f, acc3 = 0.f;

    for (int base = 0; base < d; base += 32) {
        int rem = d - base;
        int cj = (lane < rem) ? g_csrcol[s + base + lane] : 0;
        int cnt = min(32, rem);
        int j = 0;
        for (; j + 8 <= cnt; j += 8) {
            uint2 v[8];
            #pragma unroll
            for (int u = 0; u < 8; u++) {
                int col = __shfl_sync(0xffffffffu, cj, j + u);
                v[u] = *(const uint2*)&g_bufB[(size_t)col * HID + lane * 4];
            }
            #pragma unroll
            for (int u = 0; u < 8; u++) {
                float2 f0 = __half22float2(*(__half2*)&v[u].x);
                float2 f1 = __half22float2(*(__half2*)&v[u].y);
                acc0 += f0.x; acc1 += f0.y;
                acc2 += f1.x; acc3 += f1.y;
            }
        }
        for (; j < cnt; j++) {
            int col = __shfl_sync(0xffffffffu, cj, j);
            uint2 v = *(const uint2*)&g_bufB[(size_t)col * HID + lane * 4];
            float2 f0 = __half22float2(*(__half2*)&v.x);
            float2 f1 = __half22float2(*(__half2*)&v.y);
            acc0 += f0.x; acc1 += f0.y;
            acc2 += f1.x; acc3 += f1.y;
        }
    }

    const float inv = 1.f / ((float)d + 1.0f);
    uint2 pa2 = *(const uint2*)&g_bufA[(size_t)n * HID + lane * 4];
    float2 p0 = __half22float2(*(__half2*)&pa2.x);
    float2 p1 = __half22float2(*(__half2*)&pa2.y);
    // h2 row (match prior fp16 round-trip exactly for bit-stable rel_err):
    __half2 hh0 = __floats2half2_rn(fmaxf(p0.x + acc0 * inv, 0.f),
                                    fmaxf(p0.y + acc1 * inv, 0.f));
    __half2 hh1 = __floats2half2_rn(fmaxf(p1.x + acc2 * inv, 0.f),
                                    fmaxf(p1.y + acc3 * inv, 0.f));
    float2 h0 = __half22float2(hh0);
    float2 h1 = __half22float2(hh1);

    // zero this node's degree counter for the next call (we already read it)
    if (lane == 0) g_deg[n] = 0;

    // stash row in SMEM for the head
    sh[w][lane * 4 + 0] = h0.x;
    sh[w][lane * 4 + 1] = h0.y;
    sh[w][lane * 4 + 2] = h1.x;
    sh[w][lane * 4 + 3] = h1.y;
    __syncthreads();   // sW/sb staged by whole block + sh rows ready

    // ---- MLP head: 40 logits per node ----
    float v1 = sb[lane];
    float v2 = (lane < 8) ? sb[lane + 32] : -1e30f;

    const float* swr1 = &sW[lane * 129];
    #pragma unroll 8
    for (int k = 0; k < 128; k++) v1 += sh[w][k] * swr1[k];
    if (lane < 8) {
        const float* swr2 = &sW[(lane + 32) * 129];
        #pragma unroll 8
        for (int k = 0; k < 128; k++) v2 += sh[w][k] * swr2[k];
    }

    float mx = fmaxf(v1, v2);
    #pragma unroll
    for (int o = 16; o; o >>= 1) mx = fmaxf(mx, __shfl_xor_sync(0xffffffffu, mx, o));
    float sum = expf(v1 - mx) + ((lane < 8) ? expf(v2 - mx) : 0.f);
    #pragma unroll
    for (int o = 16; o; o >>= 1) sum += __shfl_xor_sync(0xffffffffu, sum, o);
    float lg = logf(sum);

    out[(size_t)n * NCLS + lane] = v1 - mx - lg;
    if (lane < 8) out[(size_t)n * NCLS + lane + 32] = v2 - mx - lg;
}

// ---------------- launch ----------------
extern "C" void kernel_launch(void* const* d_in, const int* in_sizes, int n_in,
                              void* d_out, int out_size) {
    const float* x  = (const float*)d_in[0];
    const float* W1 = (const float*)d_in[1];
    const float* W2 = (const float*)d_in[2];
    const float* mW = (const float*)d_in[3];
    const float* mb = (const float*)d_in[4];
    const int*   er = (const int*)d_in[5];
    const int*   ec = (const int*)d_in[6];
    float* out = (float*)d_out;

    // CSR build (g_deg zeroed: .bss init on first call, spmm2 re-zero after)
    k_hist<<<(EE + 255) / 256, 256>>>(er);
    k_scan1<<<(NN + 1023) / 1024, 1024>>>();
    k_scan2<<<1, 128>>>((NN + 1023) / 1024);
    k_scan3<<<(NN + 255) / 256, 256>>>();
    k_scatter<<<(EE + 255) / 256, 256>>>(er, ec);

    // Layer 1: Pa = x@Wa^T, Pb = x@Wb^T (fp16), then h1 = relu(Pa + agg(Pb)/(deg+1))
    k_gemm_mma<256, 1><<<dim3(MTILES, 2), 256>>>(x, W1);
    k_spmm1<<<(NN + 7) / 8, 256>>>();
    // Layer 2 GEMM, then fused aggregate + MLP + log_softmax
    k_gemm_mma<128, 2><<<dim3(MTILES, 2), 256>>>(x, W2);
    k_spmm2_mlp<<<NN / 8, 256>>>(mW, mb, out);
}

// round 15
// speedup vs baseline: 1.0914x; 1.0155x over previous
#include <cuda_runtime.h>
#include <cuda_fp16.h>
#include <math.h>
#include <stdint.h>

#define NN 100000
#define EE 3200000
#define HID 128
#define NCLS 40
#define MTILES 782   // ceil(100000/128)
#define KP 40        // padded SMEM row length (halves)

// ---------------- scratch (device globals; no allocation) ----------------
// g_deg is zero-initialized at module load; each warp re-zeroes its own node's
// counter at the end of the fused spmm2 (after reading it), so every call
// starts from zeros. Deterministic, race-free.
__device__ int g_deg[NN];
__device__ int g_rowstart[NN];
__device__ int g_cursor[NN];
__device__ int g_excl[NN];
__device__ int g_bsum[128];
__device__ int g_csrcol[EE];
__device__ __half g_bufA[(size_t)NN * HID];    // Pa (self-projection, fp16)
__device__ __half g_bufB[(size_t)NN * HID];    // Pb (neighbor-projection, fp16)
__device__ __half g_h1[(size_t)NN * HID];      // layer-1 activations (fp16)

// ---- side stream + events for graph fork/join (host-side objects, created
// once at static-init time; no device memory, no per-call guards) ----
static cudaStream_t g_s2;
static cudaEvent_t g_ev_fork, g_ev_join;
namespace {
struct StreamInit {
    StreamInit() {
        cudaStreamCreateWithFlags(&g_s2, cudaStreamNonBlocking);
        cudaEventCreateWithFlags(&g_ev_fork, cudaEventDisableTiming);
        cudaEventCreateWithFlags(&g_ev_join, cudaEventDisableTiming);
    }
} g_stream_init;
}

__device__ __forceinline__ uint32_t h2bits(float a, float b) {
    __half2 h = __floats2half2_rn(a, b);
    return *(uint32_t*)&h;
}

__device__ __forceinline__ void mma_f16(float* c, const uint32_t* a, const uint32_t* b) {
    asm volatile(
        "mma.sync.aligned.m16n8k16.row.col.f32.f16.f16.f32 "
        "{%0,%1,%2,%3}, {%4,%5,%6,%7}, {%8,%9}, {%0,%1,%2,%3};"
        : "+f"(c[0]), "+f"(c[1]), "+f"(c[2]), "+f"(c[3])
        : "r"(a[0]), "r"(a[1]), "r"(a[2]), "r"(a[3]), "r"(b[0]), "r"(b[1]));
}

// ---------------- CSR build ----------------
__global__ void k_hist(const int* __restrict__ rows) {
    int i = blockIdx.x * blockDim.x + threadIdx.x;
    if (i < EE) atomicAdd(&g_deg[rows[i]], 1);
}
__global__ void k_scan1() {
    __shared__ int s[1024];
    int gid = blockIdx.x * 1024 + threadIdx.x;
    int v = (gid < NN) ? g_deg[gid] : 0;
    s[threadIdx.x] = v;
    __syncthreads();
    #pragma unroll
    for (int off = 1; off < 1024; off <<= 1) {
        int t = (threadIdx.x >= off) ? s[threadIdx.x - off] : 0;
        __syncthreads();
        s[threadIdx.x] += t;
        __syncthreads();
    }
    if (gid < NN) g_excl[gid] = s[threadIdx.x] - v;
    if (threadIdx.x == 1023) g_bsum[blockIdx.x] = s[1023];
}
__global__ void k_scan2(int nb) {
    __shared__ int ws[4];
    int t = threadIdx.x;           // 128 threads
    int lane = t & 31, w = t >> 5;
    int v = (t < nb) ? g_bsum[t] : 0;
    int x = v;
    #pragma unroll
    for (int off = 1; off < 32; off <<= 1) {
        int y = __shfl_up_sync(0xffffffffu, x, off);
        if (lane >= off) x += y;
    }
    if (lane == 31) ws[w] = x;
    __syncthreads();
    int add = 0;
    for (int i = 0; i < w; i++) add += ws[i];
    if (t < nb) g_bsum[t] = x - v + add;   // exclusive scan of block sums
}
__global__ void k_scan3() {
    int gid = blockIdx.x * blockDim.x + threadIdx.x;
    if (gid < NN) {
        int rs = g_excl[gid] + g_bsum[gid >> 10];
        g_rowstart[gid] = rs;
        g_cursor[gid] = rs;
    }
}
__global__ void k_scatter(const int* __restrict__ rows, const int* __restrict__ cols) {
    int i = blockIdx.x * blockDim.x + threadIdx.x;
    if (i < EE) {
        int r = rows[i];
        int p = atomicAdd(&g_cursor[r], 1);
        g_csrcol[p] = cols[i];
    }
}

// ---------------- fp16 mma GEMM (fp32 accumulate) ----------------
// Block tile 128x128, 256 threads = 8 warps (4m x 2n), warp tile 32x64 via m16n8k16.
// blockIdx.y = 0 -> Pa = A @ Wa^T; 1 -> Pb = A @ Wb^T. Both fp16 out.
// Double-buffered half SMEM (16-k chunks), [m][k]-major with 40-half padded rows.
template <int K, int LAYER>
__global__ void __launch_bounds__(256, 2) k_gemm_mma(const float* __restrict__ xin,
                                                     const float* __restrict__ W) {
    __shared__ __half As[2][128][KP];
    __shared__ __half Bs[2][128][KP];

    const int KW = 2 * K;
    const int koff = blockIdx.y * K;
    const int mbase = blockIdx.x * 128;

    const int tid = threadIdx.x;
    const int w = tid >> 5;
    const int lane = tid & 31;
    const int wm = w & 3;
    const int wn = w >> 2;
    const int gid = lane >> 2;   // 0..7
    const int tq = lane & 3;     // 0..3

    const int lrow = tid >> 1;        // 0..127 (stage row)
    const int kb = (tid & 1) * 8;     // half-offset within 16-k chunk

    float c[2][8][4];
    #pragma unroll
    for (int i = 0; i < 2; i++)
        #pragma unroll
        for (int j = 0; j < 8; j++)
            #pragma unroll
            for (int q = 0; q < 4; q++) c[i][j][q] = 0.f;

    const int mload = min(mbase + lrow, NN - 1);
    uint32_t ra[4], rb[4];   // 8 halves each, packed half2

    auto ldg_chunk = [&](int kc) {
        if (LAYER == 1) {
            const float* src = &xin[(size_t)mload * K + kc + kb];
            float4 v0 = *(const float4*)(src);
            float4 v1 = *(const float4*)(src + 4);
            ra[0] = h2bits(v0.x, v0.y);
            ra[1] = h2bits(v0.z, v0.w);
            ra[2] = h2bits(v1.x, v1.y);
            ra[3] = h2bits(v1.z, v1.w);
        } else {
            uint4 raw = *(const uint4*)&g_h1[(size_t)mload * K + kc + kb];
            ra[0] = raw.x; ra[1] = raw.y; ra[2] = raw.z; ra[3] = raw.w;
        }
        const float* wsrc = &W[(size_t)lrow * KW + koff + kc + kb];
        float4 b0 = *(const float4*)(wsrc);
        float4 b1 = *(const float4*)(wsrc + 4);
        rb[0] = h2bits(b0.x, b0.y);
        rb[1] = h2bits(b0.z, b0.w);
        rb[2] = h2bits(b1.x, b1.y);
        rb[3] = h2bits(b1.z, b1.w);
    };
    auto sts_chunk = [&](int buf) {
        *(uint4*)&As[buf][lrow][kb] = make_uint4(ra[0], ra[1], ra[2], ra[3]);
        *(uint4*)&Bs[buf][lrow][kb] = make_uint4(rb[0], rb[1], rb[2], rb[3]);
    };
    auto compute = [&](int buf) {
        uint32_t a[2][4];
        #pragma unroll
        for (int mt = 0; mt < 2; mt++) {
            int rbv = wm * 32 + mt * 16;
            a[mt][0] = *(const uint32_t*)&As[buf][rbv + gid][2 * tq];
            a[mt][1] = *(const uint32_t*)&As[buf][rbv + gid + 8][2 * tq];
            a[mt][2] = *(const uint32_t*)&As[buf][rbv + gid][2 * tq + 8];
            a[mt][3] = *(const uint32_t*)&As[buf][rbv + gid + 8][2 * tq + 8];
        }
        #pragma unroll
        for (int nt = 0; nt < 8; nt++) {
            int nb = wn * 64 + nt * 8;
            uint32_t b[2];
            b[0] = *(const uint32_t*)&Bs[buf][nb + gid][2 * tq];
            b[1] = *(const uint32_t*)&Bs[buf][nb + gid][2 * tq + 8];
            mma_f16(c[0][nt], a[0], b);
            mma_f16(c[1][nt], a[1], b);
        }
    };

    constexpr int NCH = K / 16;
    ldg_chunk(0);
    sts_chunk(0);
    __syncthreads();
    for (int ch = 0; ch < NCH; ch++) {
        if (ch + 1 < NCH) ldg_chunk((ch + 1) * 16);   // LDG in flight during MMAs
        compute(ch & 1);
        if (ch + 1 < NCH) sts_chunk((ch + 1) & 1);
        __syncthreads();
    }

    __half* out = blockIdx.y ? g_bufB : g_bufA;
    #pragma unroll
    for (int mt = 0; mt < 2; mt++) {
        #pragma unroll
        for (int nt = 0; nt < 8; nt++) {
            int row = mbase + wm * 32 + mt * 16 + gid;
            int col = wn * 64 + nt * 8 + 2 * tq;
            if (row < NN)
                *(__half2*)&out[(size_t)row * HID + col] =
                    __floats2half2_rn(c[mt][nt][0], c[mt][nt][1]);
            if (row + 8 < NN)
                *(__half2*)&out[(size_t)(row + 8) * HID + col] =
                    __floats2half2_rn(c[mt][nt][2], c[mt][nt][3]);
        }
    }
}

// ---------------- SpMM layer 1: h1 = relu(Pa + agg(Pb)/(deg+1)), warp per node ----------------
__global__ void __launch_bounds__(256) k_spmm1() {
    const int tid = threadIdx.x;
    const int w = tid >> 5, lane = tid & 31;
    const int n = blockIdx.x * 8 + w;
    if (n >= NN) return;

    const int d = g_deg[n];
    const int s = g_rowstart[n];

    float acc0 = 0.f, acc1 = 0.f, acc2 = 0.f, acc3 = 0.f;

    for (int base = 0; base < d; base += 32) {
        int rem = d - base;
        int cj = (lane < rem) ? g_csrcol[s + base + lane] : 0;
        int cnt = min(32, rem);
        int j = 0;
        for (; j + 8 <= cnt; j += 8) {
            uint2 v[8];
            #pragma unroll
            for (int u = 0; u < 8; u++) {
                int col = __shfl_sync(0xffffffffu, cj, j + u);
                v[u] = *(const uint2*)&g_bufB[(size_t)col * HID + lane * 4];
            }
            #pragma unroll
            for (int u = 0; u < 8; u++) {
                float2 f0 = __half22float2(*(__half2*)&v[u].x);
                float2 f1 = __half22float2(*(__half2*)&v[u].y);
                acc0 += f0.x; acc1 += f0.y;
                acc2 += f1.x; acc3 += f1.y;
            }
        }
        for (; j < cnt; j++) {
            int col = __shfl_sync(0xffffffffu, cj, j);
            uint2 v = *(const uint2*)&g_bufB[(size_t)col * HID + lane * 4];
            float2 f0 = __half22float2(*(__half2*)&v.x);
            float2 f1 = __half22float2(*(__half2*)&v.y);
            acc0 += f0.x; acc1 += f0.y;
            acc2 += f1.x; acc3 += f1.y;
        }
    }

    const float inv = 1.f / ((float)d + 1.0f);
    uint2 pa2 = *(const uint2*)&g_bufA[(size_t)n * HID + lane * 4];
    float2 p0 = __half22float2(*(__half2*)&pa2.x);
    float2 p1 = __half22float2(*(__half2*)&pa2.y);
    float r0 = fmaxf(p0.x + acc0 * inv, 0.f);
    float r1 = fmaxf(p0.y + acc1 * inv, 0.f);
    float r2 = fmaxf(p1.x + acc2 * inv, 0.f);
    float r3 = fmaxf(p1.y + acc3 * inv, 0.f);

    uint2 o;
    *(__half2*)&o.x = __floats2half2_rn(r0, r1);
    *(__half2*)&o.y = __floats2half2_rn(r2, r3);
    *(uint2*)&g_h1[(size_t)n * HID + lane * 4] = o;
}

// ---------------- SpMM layer 2 FUSED with MLP + log_softmax ----------------
// Warp per node. After the gather, each warp holds h2[n] across lanes (4/lane);
// it writes the row to SMEM and computes the 40-class head directly.
// Also re-zeroes this node's g_deg entry (after reading) for the next call.
__global__ void __launch_bounds__(256) k_spmm2_mlp(const float* __restrict__ Wm,
                                                   const float* __restrict__ bias,
                                                   float* __restrict__ out) {
    __shared__ float sW[NCLS * 129];
    __shared__ float sb[NCLS];
    __shared__ float sh[8][128];

    const int tid = threadIdx.x;
    // stage MLP weights once per block (overlaps with gather issue below)
    for (int idx = tid; idx < NCLS * 128; idx += 256) {
        int cc = idx >> 7, k = idx & 127;
        sW[cc * 129 + k] = Wm[idx];
    }
    if (tid < NCLS) sb[tid] = bias[tid];

    const int w = tid >> 5, lane = tid & 31;
    const int n = blockIdx.x * 8 + w;   // NN divisible by 8: no stragglers

    const int d = g_deg[n];
    const int s = g_rowstart[n];

    float acc0 = 0.f, acc1 = 0.f, acc2 = 0.f, acc3 = 0.f;

    for (int base = 0; base < d; base += 32) {
        int rem = d - base;
        int cj = (lane < rem) ? g_csrcol[s + base + lane] : 0;
        int cnt = min(32, rem);
        int j = 0;
        for (; j + 8 <= cnt; j += 8) {
            uint2 v[8];
            #pragma unroll
            for (int u = 0; u < 8; u++) {
                int col = __shfl_sync(0xffffffffu, cj, j + u);
                v[u] = *(const uint2*)&g_bufB[(size_t)col * HID + lane * 4];
            }
            #pragma unroll
            for (int u = 0; u < 8; u++) {
                float2 f0 = __half22float2(*(__half2*)&v[u].x);
                float2 f1 = __half22float2(*(__half2*)&v[u].y);
                acc0 += f0.x; acc1 += f0.y;
                acc2 += f1.x; acc3 += f1.y;
            }
        }
        for (; j < cnt; j++) {
            int col = __shfl_sync(0xffffffffu, cj, j);
            uint2 v = *(const uint2*)&g_bufB[(size_t)col * HID + lane * 4];
            float2 f0 = __half22float2(*(__half2*)&v.x);
            float2 f1 = __half22float2(*(__half2*)&v.y);
            acc0 += f0.x; acc1 += f0.y;
            acc2 += f1.x; acc3 += f1.y;
        }
    }

    const float inv = 1.f / ((float)d + 1.0f);
    uint2 pa2 = *(const uint2*)&g_bufA[(size_t)n * HID + lane * 4];
    float2 p0 = __half22float2(*(__half2*)&pa2.x);
    float2 p1 = __half22float2(*(__half2*)&pa2.y);
    // h2 row (match prior fp16 round-trip exactly for bit-stable rel_err):
    __half2 hh0 = __floats2half2_rn(fmaxf(p0.x + acc0 * inv, 0.f),
                                    fmaxf(p0.y + acc1 * inv, 0.f));
    __half2 hh1 = __floats2half2_rn(fmaxf(p1.x + acc2 * inv, 0.f),
                                    fmaxf(p1.y + acc3 * inv, 0.f));
    float2 h0 = __half22float2(hh0);
    float2 h1 = __half22float2(hh1);

    // zero this node's degree counter for the next call (we already read it)
    if (lane == 0) g_deg[n] = 0;

    // stash row in SMEM for the head
    sh[w][lane * 4 + 0] = h0.x;
    sh[w][lane * 4 + 1] = h0.y;
    sh[w][lane * 4 + 2] = h1.x;
    sh[w][lane * 4 + 3] = h1.y;
    __syncthreads();   // sW/sb staged by whole block + sh rows ready

    // ---- MLP head: 40 logits per node ----
    float v1 = sb[lane];
    float v2 = (lane < 8) ? sb[lane + 32] : -1e30f;

    const float* swr1 = &sW[lane * 129];
    #pragma unroll 8
    for (int k = 0; k < 128; k++) v1 += sh[w][k] * swr1[k];
    if (lane < 8) {
        const float* swr2 = &sW[(lane + 32) * 129];
        #pragma unroll 8
        for (int k = 0; k < 128; k++) v2 += sh[w][k] * swr2[k];
    }

    float mx = fmaxf(v1, v2);
    #pragma unroll
    for (int o = 16; o; o >>= 1) mx = fmaxf(mx, __shfl_xor_sync(0xffffffffu, mx, o));
    float sum = expf(v1 - mx) + ((lane < 8) ? expf(v2 - mx) : 0.f);
    #pragma unroll
    for (int o = 16; o; o >>= 1) sum += __shfl_xor_sync(0xffffffffu, sum, o);
    float lg = logf(sum);

    out[(size_t)n * NCLS + lane] = v1 - mx - lg;
    if (lane < 8) out[(size_t)n * NCLS + lane + 32] = v2 - mx - lg;
}

// ---------------- launch ----------------
extern "C" void kernel_launch(void* const* d_in, const int* in_sizes, int n_in,
                              void* d_out, int out_size) {
    const float* x  = (const float*)d_in[0];
    const float* W1 = (const float*)d_in[1];
    const float* W2 = (const float*)d_in[2];
    const float* mW = (const float*)d_in[3];
    const float* mb = (const float*)d_in[4];
    const int*   er = (const int*)d_in[5];
    const int*   ec = (const int*)d_in[6];
    float* out = (float*)d_out;

    // Fork: GEMM1 (independent of graph structure) runs on side stream,
    // concurrent with the CSR build chain on the main stream.
    cudaEventRecord(g_ev_fork, 0);
    cudaStreamWaitEvent(g_s2, g_ev_fork, 0);
    k_gemm_mma<256, 1><<<dim3(MTILES, 2), 256, 0, g_s2>>>(x, W1);
    cudaEventRecord(g_ev_join, g_s2);

    // CSR build on main stream (g_deg zeroed: .bss init / spmm2 re-zero)
    k_hist<<<(EE + 255) / 256, 256>>>(er);
    k_scan1<<<(NN + 1023) / 1024, 1024>>>();
    k_scan2<<<1, 128>>>((NN + 1023) / 1024);
    k_scan3<<<(NN + 255) / 256, 256>>>();
    k_scatter<<<(EE + 255) / 256, 256>>>(er, ec);

    // Join: spmm1 needs both CSR and GEMM1 outputs
    cudaStreamWaitEvent(0, g_ev_join, 0);
    k_spmm1<<<(NN + 7) / 8, 256>>>();

    // Layer 2 GEMM, then fused aggregate + MLP + log_softmax
    k_gemm_mma<128, 2><<<dim3(MTILES, 2), 256>>>(x, W2);
    k_spmm2_mlp<<<NN / 8, 256>>>(mW, mb, out);
}